// round 1
// baseline (speedup 1.0000x reference)
#include <cuda_runtime.h>
#include <cstdint>

// Shapes (fixed): B=128, CIN=16, COUT=16, F=512, N=32, K=2
#define BB   128
#define CI   16
#define CO   16
#define FF   512
#define NN   32

// Effective weights: Weff[n,i,c,k] = sum_o W1[n,i,o,k]*W2[n,o,c]
// stored as float2 over k in layout [i][c][n]  (8192 float2 = 64 KB)
// Effective bias:  beff[n,c] = sum_o b1[n,o]*W2[n,o,c] + b2[n,c], layout [c][n]
__device__ float2 g_W[CI * CO * NN];
__device__ float  g_Bias[CO * NN];

// ---------------------------------------------------------------------------
// Prologue: fold the two convs into one effective weight/bias (tiny).
// ---------------------------------------------------------------------------
__global__ void prep_kernel(const float* __restrict__ W1, const float* __restrict__ b1,
                            const float* __restrict__ W2, const float* __restrict__ b2)
{
    int tid = blockIdx.x * blockDim.x + threadIdx.x;
    if (tid < CI * CO * NN) {
        int n = tid & 31;
        int c = (tid >> 5) & 15;
        int i = tid >> 9;
        float s0 = 0.f, s1 = 0.f;
        const float* w1 = W1 + (size_t)(n * CI + i) * CO * 2;  // + o*2 + k
        const float* w2 = W2 + (size_t)n * CO * CO + c;        // + o*16
#pragma unroll
        for (int o = 0; o < CO; ++o) {
            float wv = w2[o * CO];
            s0 = fmaf(w1[o * 2 + 0], wv, s0);
            s1 = fmaf(w1[o * 2 + 1], wv, s1);
        }
        g_W[(i * CO + c) * NN + n] = make_float2(s0, s1);
    }
    if (tid < CO * NN) {
        int n = tid & 31;
        int c = tid >> 5;
        float s = b2[n * CO + c];
#pragma unroll
        for (int o = 0; o < CO; ++o)
            s = fmaf(b1[n * CO + o], W2[(size_t)(n * CO + o) * CO + c], s);
        g_Bias[c * NN + n] = s;
    }
}

// ---------------------------------------------------------------------------
// f32x2 packed helpers (Blackwell: fma.rn.f32x2 doubles fp32 FMA throughput)
// ---------------------------------------------------------------------------
__device__ __forceinline__ uint64_t pack2(float lo, float hi) {
    uint64_t r;
    asm("mov.b64 %0, {%1, %2};" : "=l"(r) : "f"(lo), "f"(hi));
    return r;
}
__device__ __forceinline__ void ffma2(uint64_t& acc, uint64_t a, uint64_t b) {
    asm("fma.rn.f32x2 %0, %1, %2, %0;" : "+l"(acc) : "l"(a), "l"(b));
}

// ---------------------------------------------------------------------------
// Main kernel.
//  lane  = n (0..31)                -> coalesced x loads (128B) & out stores (256B)
//  warp  = (row-group of 4 f) x (c-half of 8 channels)
//  block = 256 threads = 8 warps = 4 row-groups = 16 rows of (b,f)
//  Weff staged in smem [i][c][n] float2 -> conflict-free LDS.64
// ---------------------------------------------------------------------------
__global__ __launch_bounds__(256, 2)
void up_kernel(const float* __restrict__ x, float* __restrict__ out)
{
    extern __shared__ uint64_t smem64[];
    uint64_t* sW = smem64;                      // 8192 x 8B = 64 KB
    float*    sB = (float*)(smem64 + CI * CO * NN);  // 512 floats

    const int tid = threadIdx.x;

    // cooperative stage of Weff + bias
    const uint64_t* gw = (const uint64_t*)g_W;
#pragma unroll 4
    for (int idx = tid; idx < CI * CO * NN; idx += 256)
        sW[idx] = gw[idx];
    for (int idx = tid; idx < CO * NN; idx += 256)
        sB[idx] = g_Bias[idx];
    __syncthreads();

    const int lane  = tid & 31;          // n
    const int warp  = tid >> 5;
    const int chalf = warp & 1;          // which 8 channels
    const int group = warp >> 1;         // 0..3 row-groups in block

    const int rowbase = (blockIdx.x * 4 + group) * 4;   // < 65536
    const int b = rowbase >> 9;          // rowbase / 512
    const int f = rowbase & 511;         // 4 consecutive f, same b (512 % 4 == 0)
    const int cbase = chalf * 8;

    // accumulators: 4 rows x 8 channels, packed (k0,k1)
    uint64_t acc[4][8];
#pragma unroll
    for (int c = 0; c < 8; ++c) {
        float bv = sB[(cbase + c) * NN + lane];
        uint64_t bp = pack2(bv, bv);
#pragma unroll
        for (int r = 0; r < 4; ++r) acc[r][c] = bp;
    }

    const float* xp = x + ((size_t)b * CI * FF + f) * NN + lane;

#pragma unroll
    for (int i = 0; i < CI; ++i) {
        uint64_t xv[4];
#pragma unroll
        for (int r = 0; r < 4; ++r) {
            float v = __ldg(xp + ((size_t)i * FF + r) * NN);
            xv[r] = pack2(v, v);
        }
        const uint64_t* wrow = sW + (i * CO + cbase) * NN + lane;
#pragma unroll
        for (int c = 0; c < 8; ++c) {
            uint64_t w = wrow[c * NN];
#pragma unroll
            for (int r = 0; r < 4; ++r)
                ffma2(acc[r][c], xv[r], w);
        }
    }

    // out[b, c, f+r, 2n+k]: float2 index ((b*CO + c)*FF + f + r)*NN + n
    uint64_t* op = (uint64_t*)out + ((size_t)(b * CO + cbase) * FF + f) * NN + lane;
#pragma unroll
    for (int c = 0; c < 8; ++c)
#pragma unroll
        for (int r = 0; r < 4; ++r)
            op[((size_t)c * FF + r) * NN] = acc[r][c];
}

// ---------------------------------------------------------------------------
extern "C" void kernel_launch(void* const* d_in, const int* in_sizes, int n_in,
                              void* d_out, int out_size)
{
    const float* x  = (const float*)d_in[0];
    const float* W1 = (const float*)d_in[1];
    const float* b1 = (const float*)d_in[2];
    const float* W2 = (const float*)d_in[3];
    const float* b2 = (const float*)d_in[4];
    float* out = (float*)d_out;

    prep_kernel<<<32, 256>>>(W1, b1, W2, b2);

    const int smem_bytes = CI * CO * NN * 8 + CO * NN * 4;  // 64KB + 2KB
    cudaFuncSetAttribute(up_kernel, cudaFuncAttributeMaxDynamicSharedMemorySize,
                         smem_bytes);
    // 65536 (b,f) rows / 16 rows per block
    up_kernel<<<4096, 256, smem_bytes>>>(x, out);
}

// round 2
// speedup vs baseline: 1.1488x; 1.1488x over previous
#include <cuda_runtime.h>
#include <cstdint>

// Shapes (fixed): B=128, CIN=16, COUT=16, F=512, N=32, K=2
#define BB   128
#define CI   16
#define CO   16
#define FF   512
#define NN   32

// Effective weights: Weff[n,i,c,k] = sum_o W1[n,i,o,k]*W2[n,o,c]
// stored as float2 over k in layout [i][c][n]  (8192 float2 = 64 KB)
// Effective bias:  beff[n,c] = sum_o b1[n,o]*W2[n,o,c] + b2[n,c], layout [c][n]
__device__ float2 g_W[CI * CO * NN];
__device__ float  g_Bias[CO * NN];

// ---------------------------------------------------------------------------
// Prologue: fold the two convs into one effective weight/bias (tiny).
// ---------------------------------------------------------------------------
__global__ void prep_kernel(const float* __restrict__ W1, const float* __restrict__ b1,
                            const float* __restrict__ W2, const float* __restrict__ b2)
{
    int tid = blockIdx.x * blockDim.x + threadIdx.x;
    if (tid < CI * CO * NN) {
        int n = tid & 31;
        int c = (tid >> 5) & 15;
        int i = tid >> 9;
        float s0 = 0.f, s1 = 0.f;
        const float* w1 = W1 + (size_t)(n * CI + i) * CO * 2;  // + o*2 + k
        const float* w2 = W2 + (size_t)n * CO * CO + c;        // + o*16
#pragma unroll
        for (int o = 0; o < CO; ++o) {
            float wv = w2[o * CO];
            s0 = fmaf(w1[o * 2 + 0], wv, s0);
            s1 = fmaf(w1[o * 2 + 1], wv, s1);
        }
        g_W[(i * CO + c) * NN + n] = make_float2(s0, s1);
    }
    if (tid < CO * NN) {
        int n = tid & 31;
        int c = tid >> 5;
        float s = b2[n * CO + c];
#pragma unroll
        for (int o = 0; o < CO; ++o)
            s = fmaf(b1[n * CO + o], W2[(size_t)(n * CO + o) * CO + c], s);
        g_Bias[c * NN + n] = s;
    }
}

// ---------------------------------------------------------------------------
// f32x2 packed helpers (Blackwell: fma.rn.f32x2 doubles fp32 FMA throughput)
// ---------------------------------------------------------------------------
__device__ __forceinline__ uint64_t pack2(float lo, float hi) {
    uint64_t r;
    asm("mov.b64 %0, {%1, %2};" : "=l"(r) : "f"(lo), "f"(hi));
    return r;
}
__device__ __forceinline__ void ffma2(uint64_t& acc, uint64_t a, uint64_t b) {
    asm("fma.rn.f32x2 %0, %1, %2, %0;" : "+l"(acc) : "l"(a), "l"(b));
}

// ---------------------------------------------------------------------------
// Main kernel (persistent).
//  lane = n (0..31)   -> coalesced x loads (128B) & float2 out stores (256B)
//  warp = (row-group of 8 f) x (c-quarter of 4 channels)
//  block = 256 threads = 8 warps = 2 row-groups of 8 rows = 16 rows/tile
//  Persistent: stage 64KB Weff once, grid-stride over 4096 tiles.
//  Per warp per i: 8 LDG + 4 LDS.64 + 32 FFMA2  (L1 wf balanced with fma pipe)
// ---------------------------------------------------------------------------
__global__ __launch_bounds__(256, 2)
void up_kernel(const float* __restrict__ x, float* __restrict__ out)
{
    extern __shared__ uint64_t sW[];   // 8192 x 8B = 64 KB, layout [i][c][n]

    const int tid = threadIdx.x;

    // cooperative one-time stage of Weff (16B vector copies)
    {
        const uint4* gw = (const uint4*)g_W;
        uint4* sw4 = (uint4*)sW;
#pragma unroll
        for (int idx = tid; idx < CI * CO * NN / 2; idx += 256)
            sw4[idx] = gw[idx];
    }
    __syncthreads();

    const int lane = tid & 31;           // n
    const int warp = tid >> 5;
    const int q    = warp & 3;           // c-quarter
    const int g    = warp >> 2;          // row-group (0,1)
    const int c0   = q * 4;

    // bias in registers, packed (k0,k1) duplicated
    uint64_t bp[4];
#pragma unroll
    for (int cc = 0; cc < 4; ++cc) {
        float bv = g_Bias[(c0 + cc) * NN + lane];
        bp[cc] = pack2(bv, bv);
    }

    const uint64_t* wbase = sW + c0 * NN + lane;   // + i*CO*NN + cc*NN

    for (int tile = blockIdx.x; tile < (BB * FF) / 16; tile += gridDim.x) {
        const int rowbase = tile * 16 + g * 8;     // 8 consecutive f rows, same b
        const int b = rowbase >> 9;
        const int f = rowbase & (FF - 1);

        const float*   xp = x + ((size_t)b * CI * FF + f) * NN + lane;
        uint64_t*      op = (uint64_t*)out + (((size_t)b * CO + c0) * FF + f) * NN + lane;

        uint64_t acc[8][4];
#pragma unroll
        for (int cc = 0; cc < 4; ++cc)
#pragma unroll
            for (int r = 0; r < 8; ++r) acc[r][cc] = bp[cc];

        // double-buffered x: load i+1 while doing i's FMAs
        uint64_t xv[2][8];
#pragma unroll
        for (int r = 0; r < 8; ++r) {
            float v = __ldg(xp + (size_t)r * NN);
            xv[0][r] = pack2(v, v);
        }

#pragma unroll
        for (int i = 0; i < CI; ++i) {
            uint64_t w[4];
#pragma unroll
            for (int cc = 0; cc < 4; ++cc)
                w[cc] = wbase[(i * CO + cc) * NN];

            if (i + 1 < CI) {
#pragma unroll
                for (int r = 0; r < 8; ++r) {
                    float v = __ldg(xp + ((size_t)(i + 1) * FF + r) * NN);
                    xv[(i + 1) & 1][r] = pack2(v, v);
                }
            }

#pragma unroll
            for (int cc = 0; cc < 4; ++cc)
#pragma unroll
                for (int r = 0; r < 8; ++r)
                    ffma2(acc[r][cc], xv[i & 1][r], w[cc]);
        }

        // out[b, c0+cc, f+r, 2n+k] as float2
#pragma unroll
        for (int cc = 0; cc < 4; ++cc)
#pragma unroll
            for (int r = 0; r < 8; ++r)
                op[((size_t)cc * FF + r) * NN] = acc[r][cc];
    }
}

// ---------------------------------------------------------------------------
extern "C" void kernel_launch(void* const* d_in, const int* in_sizes, int n_in,
                              void* d_out, int out_size)
{
    const float* x  = (const float*)d_in[0];
    const float* W1 = (const float*)d_in[1];
    const float* b1 = (const float*)d_in[2];
    const float* W2 = (const float*)d_in[3];
    const float* b2 = (const float*)d_in[4];
    float* out = (float*)d_out;

    prep_kernel<<<32, 256>>>(W1, b1, W2, b2);

    const int smem_bytes = CI * CO * NN * 8;   // 64 KB
    static int configured = -1;
    cudaFuncSetAttribute(up_kernel, cudaFuncAttributeMaxDynamicSharedMemorySize,
                         smem_bytes);
    (void)configured;

    // persistent: 2 blocks per SM (152 SMs on GB300)
    up_kernel<<<304, 256, smem_bytes>>>(x, out);
}